// round 6
// baseline (speedup 1.0000x reference)
#include <cuda_runtime.h>
#include <cstdint>

// Problem constants: B=64, R=32, N=16384, D=64, O=8
#define PB 64
#define PR 32
#define PN 16384
#define PD 64
#define PO 8

#define BLOCKS_PER_B 4
#define THREADS 512          // 16 warps
#define WARPS (THREADS / 32)

// Global scratch (zero-initialized at load; finalizing block resets each run).
__device__ float        g_dot[PB][PR];   // partial dot(norm_l[b,r], s_partial)
__device__ float        g_cnt[PB];
__device__ unsigned int g_ticket[PB];

// ---------------------------------------------------------------------------
// Grid (BLOCKS_PER_B, PB), 512 threads. Per warp: 256 rows = 2 int4 triplets
// per lane, front-batched together with the warp's 2 l_local rows (MLP 8).
// Valid rows (~0.74%) are ballot-compact gathered, L2-normalized, accumulated
// into a block-partial s (smem). Each block then converts its partial s into
// 32 partial dot-products against normalized l_local rows and atomically
// accumulates SCALARS into g_dot — so the last block's tail is one 128B read
// plus 32 scalar ops.
// ---------------------------------------------------------------------------
__global__ __launch_bounds__(THREADS)
void ssfw_fused_kernel(const float* __restrict__ l_local,
                       const float* __restrict__ h_context,
                       const float* __restrict__ lambda_so,
                       const int* __restrict__ center_o,
                       const int* __restrict__ o_types,
                       const int* __restrict__ adj_mask,
                       const int* __restrict__ two_hop_mask,
                       float* __restrict__ out) {
    __shared__ float s[PD];
    __shared__ float scnt;
    __shared__ int   sIsLast;

    const int b    = blockIdx.y;
    const int lane = threadIdx.x & 31;
    const int warp = threadIdx.x >> 5;   // 0..15

    if (threadIdx.x < PD) s[threadIdx.x] = 0.0f;
    if (threadIdx.x == 0) scnt = 0.0f;

    // ---- front-batched independent loads ----
    const int rowsPerBlock = PN / BLOCKS_PER_B;            // 4096
    const int rowsPerWarp  = rowsPerBlock / WARPS;         // 256
    const int base         = blockIdx.x * rowsPerBlock + warp * rowsPerWarp;
    const int vec0         = (base >> 2) + lane;           // first 128 rows
    const int vec1         = vec0 + 32;                    // next 128 rows

    const int4* ot4 = (const int4*)(o_types      + (size_t)b * PN);
    const int4* am4 = (const int4*)(adj_mask     + (size_t)b * PN);
    const int4* th4 = (const int4*)(two_hop_mask + (size_t)b * PN);

    const int4 ota = __ldg(&ot4[vec0]);
    const int4 ama = __ldg(&am4[vec0]);
    const int4 tha = __ldg(&th4[vec0]);
    const int4 otb = __ldg(&ot4[vec1]);
    const int4 amb = __ldg(&am4[vec1]);
    const int4 thb = __ldg(&th4[vec1]);

    // warp's 2 l_local rows (r = 2*warp, 2*warp+1), lane -> float2 slice
    const int r0 = 2 * warp;
    const float2 lv0 =
        ((const float2*)(l_local + ((size_t)b * PR + r0) * PD))[lane];
    const float2 lv1 =
        ((const float2*)(l_local + ((size_t)b * PR + r0 + 1) * PD))[lane];

    const int cb = center_o[b];

    const bool va0 = ((ama.x | tha.x) != 0) && (ota.x == cb);
    const bool va1 = ((ama.y | tha.y) != 0) && (ota.y == cb);
    const bool va2 = ((ama.z | tha.z) != 0) && (ota.z == cb);
    const bool va3 = ((ama.w | tha.w) != 0) && (ota.w == cb);
    const bool vb0 = ((amb.x | thb.x) != 0) && (otb.x == cb);
    const bool vb1 = ((amb.y | thb.y) != 0) && (otb.y == cb);
    const bool vb2 = ((amb.z | thb.z) != 0) && (otb.z == cb);
    const bool vb3 = ((amb.w | thb.w) != 0) && (otb.w == cb);

    float accx = 0.0f, accy = 0.0f;
    int   cntw = 0;                      // warp count (uniform, via popc)

    __syncthreads();   // smem zero-init visible

    const float* ctxBase = h_context + (size_t)b * PN * PD;

    #pragma unroll
    for (int t = 0; t < 8; ++t) {
        bool vt;
        int  rb;
        switch (t) {
            case 0: vt = va0; rb = base;           break;
            case 1: vt = va1; rb = base;           break;
            case 2: vt = va2; rb = base;           break;
            case 3: vt = va3; rb = base;           break;
            case 4: vt = vb0; rb = base + 128;     break;
            case 5: vt = vb1; rb = base + 128;     break;
            case 6: vt = vb2; rb = base + 128;     break;
            default: vt = vb3; rb = base + 128;    break;
        }
        const int sub = t & 3;
        unsigned m = __ballot_sync(0xffffffffu, vt);
        cntw += __popc(m);
        while (m) {
            const int j = __ffs(m) - 1;
            m &= (m - 1);
            const int row = rb + 4 * j + sub;
            const float2 v = ((const float2*)(ctxBase + (size_t)row * PD))[lane];
            float ss = v.x * v.x + v.y * v.y;
            #pragma unroll
            for (int o = 16; o; o >>= 1)
                ss += __shfl_xor_sync(0xffffffffu, ss, o);
            const float inv = rsqrtf(fmaxf(ss, 1e-12f));
            accx += v.x * inv;
            accy += v.y * inv;
        }
    }

    // block-partial s in smem
    atomicAdd(&s[2 * lane],     accx);
    atomicAdd(&s[2 * lane + 1], accy);
    if (lane == 0) atomicAdd(&scnt, (float)cntw);
    __syncthreads();

    // ---- partial dots: warp handles rows r0, r0+1 against block-partial s ----
    const float sx = s[2 * lane];
    const float sy = s[2 * lane + 1];

    float ss0 = lv0.x * lv0.x + lv0.y * lv0.y;
    float dt0 = lv0.x * sx + lv0.y * sy;
    float ss1 = lv1.x * lv1.x + lv1.y * lv1.y;
    float dt1 = lv1.x * sx + lv1.y * sy;
    #pragma unroll
    for (int o = 16; o; o >>= 1) {
        ss0 += __shfl_xor_sync(0xffffffffu, ss0, o);
        dt0 += __shfl_xor_sync(0xffffffffu, dt0, o);
        ss1 += __shfl_xor_sync(0xffffffffu, ss1, o);
        dt1 += __shfl_xor_sync(0xffffffffu, dt1, o);
    }
    if (lane == 0) {
        atomicAdd(&g_dot[b][r0],     dt0 * rsqrtf(fmaxf(ss0, 1e-12f)));
        atomicAdd(&g_dot[b][r0 + 1], dt1 * rsqrtf(fmaxf(ss1, 1e-12f)));
    }
    if (threadIdx.x == 0) atomicAdd(&g_cnt[b], scnt);

    __threadfence();
    __syncthreads();
    if (threadIdx.x == 0) {
        const unsigned old = atomicAdd(&g_ticket[b], 1u);
        sIsLast = (old == BLOCKS_PER_B - 1);
    }
    __syncthreads();
    if (!sIsLast) return;

    // ---- tail (last block per b): one 128B sector + 32 scalar ops ----
    __threadfence();
    if (threadIdx.x < PR) {
        const int   r    = threadIdx.x;
        const float cntf = g_cnt[b];
        const float nd   = g_dot[b][r];
        const float avg  = nd / fmaxf(cntf, 1e-9f);
        const float lam  = lambda_so[r * PO + cb];
        out[b * PR + r]  = fmaxf(lam / fmaxf(cntf, 1.0f), 0.0f) * (1.0f - avg);
        // reset scratch for next graph replay
        g_dot[b][r] = 0.0f;
        if (r == 0) { g_cnt[b] = 0.0f; g_ticket[b] = 0u; }
    }
}

// ---------------------------------------------------------------------------
// Launch. Input order: l_local, h_context, lambda_so, center_o, o_types,
//                      adj_mask, two_hop_mask
// ---------------------------------------------------------------------------
extern "C" void kernel_launch(void* const* d_in, const int* in_sizes, int n_in,
                              void* d_out, int out_size) {
    const float* l_local   = (const float*)d_in[0];
    const float* h_context = (const float*)d_in[1];
    const float* lambda_so = (const float*)d_in[2];
    const int*   center_o  = (const int*)d_in[3];
    const int*   o_types   = (const int*)d_in[4];
    const int*   adj_mask  = (const int*)d_in[5];
    const int*   two_hop   = (const int*)d_in[6];
    float*       out       = (float*)d_out;

    dim3 grid(BLOCKS_PER_B, PB);
    ssfw_fused_kernel<<<grid, THREADS>>>(l_local, h_context, lambda_so,
                                         center_o, o_types, adj_mask, two_hop,
                                         out);
}

// round 7
// speedup vs baseline: 1.2112x; 1.2112x over previous
#include <cuda_runtime.h>
#include <cstdint>

// Problem constants: B=64, R=32, N=16384, D=64, O=8
#define PB 64
#define PR 32
#define PN 16384
#define PD 64
#define PO 8

#define BLOCKS_PER_B 16
#define THREADS 256          // 8 warps
#define WARPS (THREADS / 32)

// Global scratch (zero-initialized at load; the finalizing block resets it
// each run -> graph-replay-deterministic).
__device__ float        g_s[PB][PD];
__device__ float        g_cnt[PB];
__device__ unsigned int g_ticket[PB];

// acq_rel fetch-add on the ticket: release orders this block's prior global
// atomics before the bump; acquire on the returned value orders the
// finalizer's subsequent reads. Replaces two __threadfence() calls.
__device__ __forceinline__ unsigned int ticket_acq_rel(unsigned int* p) {
    unsigned int old;
    asm volatile("atom.acq_rel.gpu.global.add.u32 %0, [%1], 1;"
                 : "=r"(old) : "l"(p) : "memory");
    return old;
}

// ---------------------------------------------------------------------------
// Grid (BLOCKS_PER_B, PB), 256 threads. Each warp covers exactly 128 rows:
// one int4 (LDG.128) per lane from each of the 3 mask streams, all issued
// back-to-back (max MLP). Ballot-compacted gather of the ~0.74% valid
// h_context rows, warp L2-normalize, smem reduction, global atomics.
// Last block per b (acq_rel ticket) finalizes 32 outputs and resets scratch.
// ---------------------------------------------------------------------------
__global__ __launch_bounds__(THREADS)
void ssfw_fused_kernel(const float* __restrict__ l_local,
                       const float* __restrict__ h_context,
                       const float* __restrict__ lambda_so,
                       const int* __restrict__ center_o,
                       const int* __restrict__ o_types,
                       const int* __restrict__ adj_mask,
                       const int* __restrict__ two_hop_mask,
                       float* __restrict__ out) {
    __shared__ float s[PD];
    __shared__ float scnt;
    __shared__ int   sIsLast;

    const int b    = blockIdx.y;
    const int lane = threadIdx.x & 31;
    const int warp = threadIdx.x >> 5;

    if (threadIdx.x < PD) s[threadIdx.x] = 0.0f;
    if (threadIdx.x == 0) scnt = 0.0f;

    const int cb = center_o[b];

    // ---- Phase 1: masked scan, one int4 triplet per lane ----
    const int rowsPerBlock = PN / BLOCKS_PER_B;            // 1024
    const int rowsPerWarp  = rowsPerBlock / WARPS;         // 128
    const int base         = blockIdx.x * rowsPerBlock + warp * rowsPerWarp;
    const int vec          = (base >> 2) + lane;           // int4 index

    const int4* ot4 = (const int4*)(o_types      + (size_t)b * PN);
    const int4* am4 = (const int4*)(adj_mask     + (size_t)b * PN);
    const int4* th4 = (const int4*)(two_hop_mask + (size_t)b * PN);

    // three independent LDG.128 issued back-to-back
    const int4 ot = __ldg(&ot4[vec]);
    const int4 am = __ldg(&am4[vec]);
    const int4 th = __ldg(&th4[vec]);

    const bool v0 = ((am.x | th.x) != 0) && (ot.x == cb);
    const bool v1 = ((am.y | th.y) != 0) && (ot.y == cb);
    const bool v2 = ((am.z | th.z) != 0) && (ot.z == cb);
    const bool v3 = ((am.w | th.w) != 0) && (ot.w == cb);

    float accx = 0.0f, accy = 0.0f;
    int   cntw = 0;

    __syncthreads();   // smem zero-init visible

    const float* ctxBase = h_context + (size_t)b * PN * PD;

    #pragma unroll
    for (int t = 0; t < 4; ++t) {
        const bool vt = (t == 0) ? v0 : (t == 1) ? v1 : (t == 2) ? v2 : v3;
        unsigned m = __ballot_sync(0xffffffffu, vt);
        cntw += __popc(m);
        while (m) {
            const int j = __ffs(m) - 1;
            m &= (m - 1);
            const int row = base + 4 * j + t;
            // warp cooperatively loads this 256B row: lane -> float2 slice
            const float2 v = ((const float2*)(ctxBase + (size_t)row * PD))[lane];
            float ss = v.x * v.x + v.y * v.y;
            #pragma unroll
            for (int o = 16; o; o >>= 1)
                ss += __shfl_xor_sync(0xffffffffu, ss, o);
            const float inv = rsqrtf(fmaxf(ss, 1e-12f));
            accx += v.x * inv;
            accy += v.y * inv;
        }
    }

    // block-local reduction into smem
    atomicAdd(&s[2 * lane],     accx);
    atomicAdd(&s[2 * lane + 1], accy);
    if (lane == 0) atomicAdd(&scnt, (float)cntw);
    __syncthreads();

    // warp 0 pushes the block partial to global scratch; thread 0 then bumps
    // the ticket with acq_rel (orders the pushes without __threadfence).
    if (warp == 0) {
        atomicAdd(&g_s[b][2 * lane],     s[2 * lane]);
        atomicAdd(&g_s[b][2 * lane + 1], s[2 * lane + 1]);
        if (lane == 0) {
            atomicAdd(&g_cnt[b], scnt);
            const unsigned old = ticket_acq_rel(&g_ticket[b]);
            sIsLast = (old == BLOCKS_PER_B - 1);
        }
    }
    __syncthreads();
    if (!sIsLast) return;

    // ---- Phase 2 (last block per b): finalize 32 outputs ----
    const float cntf  = g_cnt[b];
    const float invc9 = 1.0f / fmaxf(cntf, 1e-9f);
    const float invc1 = 1.0f / fmaxf(cntf, 1.0f);

    const float sx = g_s[b][2 * lane];
    const float sy = g_s[b][2 * lane + 1];

    #pragma unroll
    for (int rr = 0; rr < PR / WARPS; ++rr) {          // 4 rows per warp
        const int r = warp + rr * WARPS;
        const float2 v =
            ((const float2*)(l_local + ((size_t)b * PR + r) * PD))[lane];
        float ss  = v.x * v.x + v.y * v.y;
        float dot = v.x * sx + v.y * sy;
        #pragma unroll
        for (int o = 16; o; o >>= 1) {
            ss  += __shfl_xor_sync(0xffffffffu, ss,  o);
            dot += __shfl_xor_sync(0xffffffffu, dot, o);
        }
        if (lane == 0) {
            const float inv = rsqrtf(fmaxf(ss, 1e-12f));
            const float avg = dot * inv * invc9;
            const float lam = lambda_so[r * PO + cb];
            out[b * PR + r] = fmaxf(lam * invc1, 0.0f) * (1.0f - avg);
        }
    }

    // ---- reset scratch for the next (graph-replayed) run ----
    __syncthreads();
    if (threadIdx.x < PD) g_s[b][threadIdx.x] = 0.0f;
    if (threadIdx.x == 0) { g_cnt[b] = 0.0f; g_ticket[b] = 0u; }
}

// ---------------------------------------------------------------------------
// Launch. Input order: l_local, h_context, lambda_so, center_o, o_types,
//                      adj_mask, two_hop_mask
// ---------------------------------------------------------------------------
extern "C" void kernel_launch(void* const* d_in, const int* in_sizes, int n_in,
                              void* d_out, int out_size) {
    const float* l_local   = (const float*)d_in[0];
    const float* h_context = (const float*)d_in[1];
    const float* lambda_so = (const float*)d_in[2];
    const int*   center_o  = (const int*)d_in[3];
    const int*   o_types   = (const int*)d_in[4];
    const int*   adj_mask  = (const int*)d_in[5];
    const int*   two_hop   = (const int*)d_in[6];
    float*       out       = (float*)d_out;

    dim3 grid(BLOCKS_PER_B, PB);
    ssfw_fused_kernel<<<grid, THREADS>>>(l_local, h_context, lambda_so,
                                         center_o, o_types, adj_mask, two_hop,
                                         out);
}